// round 1
// baseline (speedup 1.0000x reference)
#include <cuda_runtime.h>
#include <stdint.h>

// Problem constants (shapes fixed by reference)
#define D 128          // node feature dim == edge feature dim
#define C 10           // classes
#define WIN 384        // 2*D + edim
#define MAX_NODES 100000
#define PSTR 16        // padded stride for P/Q rows (16 floats = 64B, aligned)

// Scratch (allocation-free rule: __device__ globals)
__device__ float g_P[MAX_NODES * PSTR];   // h . Wu^T + b
__device__ float g_Q[MAX_NODES * PSTR];   // h . Wv^T
__device__ int   g_is64;

// ---------- packed fp32 helpers (sm_100+ f32x2 pipe, 2x FFMA throughput) ----
__device__ __forceinline__ void ffma2(unsigned long long& d,
                                      unsigned long long a,
                                      unsigned long long b) {
    asm("fma.rn.f32x2 %0, %1, %2, %0;" : "+l"(d) : "l"(a), "l"(b));
}
__device__ __forceinline__ float f2sum(unsigned long long v) {
    return __uint_as_float((unsigned)v) + __uint_as_float((unsigned)(v >> 32));
}

// ---------- dtype sniffing: int64 vs int32 indices ---------------------------
__global__ void detect_kernel(const unsigned long long* __restrict__ idx) {
    if (threadIdx.x == 0 && blockIdx.x == 0) {
        int ok = 1;
#pragma unroll
        for (int i = 0; i < 64; i++)
            if ((idx[i] >> 32) != 0ULL) ok = 0;
        g_is64 = ok;
    }
}

// ---------- stage 1: per-node projections P = h.Wu^T + b, Q = h.Wv^T --------
__global__ void __launch_bounds__(128)
node_proj_kernel(const float* __restrict__ h,
                 const float* __restrict__ W,
                 const float* __restrict__ b,
                 int N) {
    __shared__ float sW[20 * D];  // 10 KB: Wu rows 0..9, Wv rows 10..19
    for (int i = threadIdx.x; i < 20 * D; i += blockDim.x) {
        int c = i >> 7, k = i & 127;
        sW[i] = (c < 10) ? W[c * WIN + k] : W[(c - 10) * WIN + D + k];
    }
    __syncthreads();

    int n = blockIdx.x * blockDim.x + threadIdx.x;
    if (n >= N) return;

    unsigned long long acc[20];
#pragma unroll
    for (int c = 0; c < 20; c++) acc[c] = 0ULL;

    const ulonglong2* hp = (const ulonglong2*)(h + (size_t)n * D);
#pragma unroll 4
    for (int k4 = 0; k4 < D / 4; k4++) {
        ulonglong2 hv = hp[k4];
#pragma unroll
        for (int c = 0; c < 20; c++) {
            ulonglong2 w = *(const ulonglong2*)&sW[c * D + k4 * 4];
            ffma2(acc[c], hv.x, w.x);
            ffma2(acc[c], hv.y, w.y);
        }
    }
    float* P = g_P + (size_t)n * PSTR;
    float* Q = g_Q + (size_t)n * PSTR;
#pragma unroll
    for (int c = 0; c < C; c++) {
        P[c] = f2sum(acc[c]) + __ldg(b + c);
        Q[c] = f2sum(acc[10 + c]);
    }
}

// ---------- stage 2: per-edge  out = e.We^T + P[src] + Q[dst] ----------------
__global__ void __launch_bounds__(256)
edge_kernel(const float* __restrict__ eh,
            const float* __restrict__ W,
            const void* __restrict__ src,
            const void* __restrict__ dst,
            float* __restrict__ out,
            int E) {
    __shared__ float sW[C * D];  // 5 KB: We
    for (int i = threadIdx.x; i < C * D; i += blockDim.x) {
        int c = i >> 7, k = i & 127;
        sW[i] = W[c * WIN + 2 * D + k];
    }
    __syncthreads();

    int e = blockIdx.x * blockDim.x + threadIdx.x;
    if (e >= E) return;

    long s, d;
    if (g_is64) {
        s = (long)((const long long*)src)[e];
        d = (long)((const long long*)dst)[e];
    } else {
        s = ((const int*)src)[e];
        d = ((const int*)dst)[e];
    }

    unsigned long long acc[C];
#pragma unroll
    for (int c = 0; c < C; c++) acc[c] = 0ULL;

    const ulonglong2* ep = (const ulonglong2*)(eh + (size_t)e * D);
#pragma unroll 4
    for (int k4 = 0; k4 < D / 4; k4++) {
        ulonglong2 ev = ep[k4];
#pragma unroll
        for (int c = 0; c < C; c++) {
            ulonglong2 w = *(const ulonglong2*)&sW[c * D + k4 * 4];
            ffma2(acc[c], ev.x, w.x);
            ffma2(acc[c], ev.y, w.y);
        }
    }

    // gather L2-resident node projections (64B-aligned rows)
    const float2* Pp = (const float2*)(g_P + (size_t)s * PSTR);
    const float2* Qp = (const float2*)(g_Q + (size_t)d * PSTR);
    float2* op = (float2*)(out + (size_t)e * C);
#pragma unroll
    for (int i = 0; i < C / 2; i++) {
        float2 p = Pp[i];
        float2 q = Qp[i];
        float2 r;
        r.x = f2sum(acc[2 * i])     + p.x + q.x;
        r.y = f2sum(acc[2 * i + 1]) + p.y + q.y;
        op[i] = r;
    }
}

extern "C" void kernel_launch(void* const* d_in, const int* in_sizes, int n_in,
                              void* d_out, int out_size) {
    const float* h   = (const float*)d_in[0];
    const float* eh  = (const float*)d_in[1];
    const float* Ww  = (const float*)d_in[2];
    const float* Wb  = (const float*)d_in[3];
    const void*  src = d_in[4];
    const void*  dst = d_in[5];

    int N = in_sizes[0] / D;   // 100000
    int E = in_sizes[1] / D;   // 600000

    detect_kernel<<<1, 32>>>((const unsigned long long*)src);
    node_proj_kernel<<<(N + 127) / 128, 128>>>(h, Ww, Wb, N);
    edge_kernel<<<(E + 255) / 256, 256>>>(eh, Ww, src, dst, (float*)d_out, E);
}

// round 2
// speedup vs baseline: 1.1036x; 1.1036x over previous
#include <cuda_runtime.h>
#include <stdint.h>

#define D 128          // feature dim (node == edge)
#define C 10           // classes
#define WIN 384        // 2*D + edim
#define MAX_NODES 100000
#define PSTR 12        // padded row stride for P/Q (48B, 16B-aligned)
#define SSTR 20        // smem stride (floats) for 16-feature chunks: bank-conflict-free

// Scratch: __device__ globals (allocation-free rule)
__device__ float g_P[MAX_NODES * PSTR];   // h.Wu^T + b
__device__ float g_Q[MAX_NODES * PSTR];   // h.Wv^T
__device__ int   g_is64;

// packed fp32 FMA (2x FFMA throughput; ptxas never auto-fuses f32x2)
__device__ __forceinline__ void ffma2(unsigned long long& d,
                                      unsigned long long a,
                                      unsigned long long b) {
    asm("fma.rn.f32x2 %0, %1, %2, %0;" : "+l"(d) : "l"(a), "l"(b));
}
__device__ __forceinline__ float f2sum(unsigned long long v) {
    return __uint_as_float((unsigned)v) + __uint_as_float((unsigned)(v >> 32));
}

// accumulate one padded P/Q row (10 useful floats) into r[]
__device__ __forceinline__ void addrow(const float* __restrict__ base, long idx,
                                       float* r) {
    const float4* p = (const float4*)(base + (size_t)idx * PSTR);
    float4 a = p[0], bq = p[1], cq = p[2];
    r[0] += a.x;  r[1] += a.y;  r[2] += a.z;  r[3] += a.w;
    r[4] += bq.x; r[5] += bq.y; r[6] += bq.z; r[7] += bq.w;
    r[8] += cq.x; r[9] += cq.y;
}

// ---------------- stage 1: node projections (+ dtype sniff in block 0) ------
__global__ void __launch_bounds__(256)
node_kernel(const float* __restrict__ h,
            const float* __restrict__ W,
            const float* __restrict__ b,
            int N,
            const unsigned long long* __restrict__ idx_probe) {
    __shared__ alignas(16) float sW[20 * D];    // 10 KB: Wu rows 0..9, Wv 10..19
    __shared__ alignas(16) float sN[256 * SSTR]; // 20 KB staged node features

    if (blockIdx.x == 0 && threadIdx.x == 0) {
        int ok = 1;
#pragma unroll
        for (int i = 0; i < 64; i++)
            if ((idx_probe[i] >> 32) != 0ULL) ok = 0;
        g_is64 = ok;                            // consumed by edge kernel (next launch)
    }

    int t = threadIdx.x;
    for (int i = t; i < 20 * D; i += 256) {
        int c = i >> 7, k = i & 127;
        sW[i] = (c < 10) ? W[c * WIN + k] : W[(c - 10) * WIN + D + k];
    }

    int n0 = blockIdx.x * 256;
    unsigned long long acc[20];
#pragma unroll
    for (int c = 0; c < 20; c++) acc[c] = 0ULL;

#pragma unroll 1
    for (int ch = 0; ch < 8; ch++) {            // 16-feature chunks
        __syncthreads();
        // stage 256 nodes x 64B, coalesced: 4 iterations of 256x16B
#pragma unroll
        for (int it = 0; it < 4; it++) {
            int idx = it * 256 + t;
            int e = idx >> 2, q = idx & 3;
            int gn = n0 + e;
            float4 v = (gn < N) ? *(const float4*)(h + (size_t)gn * D + ch * 16 + q * 4)
                                : make_float4(0.f, 0.f, 0.f, 0.f);
            *(float4*)&sN[e * SSTR + q * 4] = v;
        }
        __syncthreads();
#pragma unroll
        for (int k4 = 0; k4 < 4; k4++) {
            int kf = ch * 16 + k4 * 4;
            ulonglong2 v = *(const ulonglong2*)&sN[t * SSTR + k4 * 4];
#pragma unroll
            for (int c = 0; c < 20; c++) {
                ulonglong2 w = *(const ulonglong2*)&sW[c * D + kf];
                ffma2(acc[c], v.x, w.x);
                ffma2(acc[c], v.y, w.y);
            }
        }
    }

    int n = n0 + t;
    if (n >= N) return;
    float4* Pp = (float4*)(g_P + (size_t)n * PSTR);
    float4* Qp = (float4*)(g_Q + (size_t)n * PSTR);
    float r[10], s[10];
#pragma unroll
    for (int c = 0; c < 10; c++) {
        r[c] = f2sum(acc[c]) + __ldg(b + c);
        s[c] = f2sum(acc[10 + c]);
    }
    Pp[0] = make_float4(r[0], r[1], r[2], r[3]);
    Pp[1] = make_float4(r[4], r[5], r[6], r[7]);
    Pp[2] = make_float4(r[8], r[9], 0.f, 0.f);
    Qp[0] = make_float4(s[0], s[1], s[2], s[3]);
    Qp[1] = make_float4(s[4], s[5], s[6], s[7]);
    Qp[2] = make_float4(s[8], s[9], 0.f, 0.f);
}

// ---------------- stage 2: per-edge  out = eh.We^T + P[src] + Q[dst] --------
#define EB 512          // edges per block (2 per thread)

__global__ void __launch_bounds__(256)
edge_kernel(const float* __restrict__ eh,
            const float* __restrict__ W,
            const void* __restrict__ src,
            const void* __restrict__ dst,
            float* __restrict__ out,
            int E) {
    __shared__ alignas(16) float sW[C * D];      // 5 KB: We
    __shared__ alignas(16) float sE[EB * SSTR];  // 40 KB staged edge features

    int t = threadIdx.x;
    for (int i = t; i < C * D; i += 256) {
        int c = i >> 7, k = i & 127;
        sW[i] = W[c * WIN + 2 * D + k];
    }

    int e0 = blockIdx.x * EB;
    unsigned long long acc[2][C];
#pragma unroll
    for (int j = 0; j < 2; j++)
#pragma unroll
        for (int c = 0; c < C; c++) acc[j][c] = 0ULL;

#pragma unroll 1
    for (int ch = 0; ch < 8; ch++) {
        __syncthreads();
        // stage 512 edges x 64B, coalesced: 8 iterations of 256x16B
#pragma unroll
        for (int it = 0; it < 8; it++) {
            int idx = it * 256 + t;
            int e = idx >> 2, q = idx & 3;
            int ge = e0 + e;
            float4 v = (ge < E) ? *(const float4*)(eh + (size_t)ge * D + ch * 16 + q * 4)
                                : make_float4(0.f, 0.f, 0.f, 0.f);
            *(float4*)&sE[e * SSTR + q * 4] = v;
        }
        __syncthreads();
#pragma unroll
        for (int k4 = 0; k4 < 4; k4++) {
            int kf = ch * 16 + k4 * 4;
            ulonglong2 va = *(const ulonglong2*)&sE[t * SSTR + k4 * 4];
            ulonglong2 vb = *(const ulonglong2*)&sE[(t + 256) * SSTR + k4 * 4];
#pragma unroll
            for (int c = 0; c < C; c++) {
                ulonglong2 w = *(const ulonglong2*)&sW[c * D + kf];
                ffma2(acc[0][c], va.x, w.x);
                ffma2(acc[0][c], va.y, w.y);
                ffma2(acc[1][c], vb.x, w.x);
                ffma2(acc[1][c], vb.y, w.y);
            }
        }
    }

    int is64 = g_is64;
#pragma unroll
    for (int j = 0; j < 2; j++) {
        int e = e0 + t + j * 256;
        if (e >= E) continue;
        long s, d;
        if (is64) {
            s = (long)((const long long*)src)[e];
            d = (long)((const long long*)dst)[e];
        } else {
            s = ((const int*)src)[e];
            d = ((const int*)dst)[e];
        }
        float r[10];
#pragma unroll
        for (int c = 0; c < C; c++) r[c] = f2sum(acc[j][c]);
        addrow(g_P, s, r);
        addrow(g_Q, d, r);
        float2* op = (float2*)(out + (size_t)e * C);
#pragma unroll
        for (int i = 0; i < 5; i++)
            op[i] = make_float2(r[2 * i], r[2 * i + 1]);
    }
}

extern "C" void kernel_launch(void* const* d_in, const int* in_sizes, int n_in,
                              void* d_out, int out_size) {
    const float* h   = (const float*)d_in[0];
    const float* eh  = (const float*)d_in[1];
    const float* Ww  = (const float*)d_in[2];
    const float* Wb  = (const float*)d_in[3];
    const void*  src = d_in[4];
    const void*  dst = d_in[5];

    int N = in_sizes[0] / D;   // 100000
    int E = in_sizes[1] / D;   // 600000

    node_kernel<<<(N + 255) / 256, 256>>>(h, Ww, Wb, N,
                                          (const unsigned long long*)src);
    edge_kernel<<<(E + EB - 1) / EB, 256>>>(eh, Ww, src, dst, (float*)d_out, E);
}

// round 4
// speedup vs baseline: 1.3475x; 1.2210x over previous
#include <cuda_runtime.h>
#include <stdint.h>

#define D 128
#define C 10
#define WIN 384          // 2*D + edim
#define MAX_NODES 100000
#define PSTR 12          // P/Q row stride (48B, 16B multiple)
#define SSTR 20          // staged-feature stride (floats): conflict-free LDS.128
#define EPB 256          // edges/nodes per block (1 per thread)

__device__ float g_P[MAX_NODES * PSTR];
__device__ float g_Q[MAX_NODES * PSTR];
__device__ int   g_is64;

// ---- packed fp32 fma ---------------------------------------------------------
__device__ __forceinline__ void ffma2(unsigned long long& d,
                                      unsigned long long a,
                                      unsigned long long b) {
    asm("fma.rn.f32x2 %0, %1, %2, %0;" : "+l"(d) : "l"(a), "l"(b));
}
__device__ __forceinline__ float f2sum(unsigned long long v) {
    return __uint_as_float((unsigned)v) + __uint_as_float((unsigned)(v >> 32));
}

// ---- cp.async helpers --------------------------------------------------------
__device__ __forceinline__ unsigned sptr(const void* p) {
    return (unsigned)__cvta_generic_to_shared(p);
}
__device__ __forceinline__ void cpa16(unsigned dst, const void* src) {
    asm volatile("cp.async.ca.shared.global [%0], [%1], 16;" :: "r"(dst), "l"(src));
}
__device__ __forceinline__ void cpa_commit() {
    asm volatile("cp.async.commit_group;");
}
__device__ __forceinline__ void cpa_wait1() {
    asm volatile("cp.async.wait_group 1;");
}
__device__ __forceinline__ void cpa_wait0() {
    asm volatile("cp.async.wait_group 0;");
}

// stage 64B chunk `ch` of rows [r0, r0+256) of a [*, 128] fp32 matrix
__device__ __forceinline__ void stage_chunk(float* dstbuf, const float* __restrict__ m,
                                            long r0, int ch, int t, int nmax) {
#pragma unroll
    for (int it = 0; it < 4; it++) {
        int idx = it * 256 + t;
        int e = idx >> 2, q = idx & 3;
        long gr = r0 + e;
        if (gr > nmax) gr = nmax;
        cpa16(sptr(&dstbuf[e * SSTR + q * 4]),
              m + gr * D + ch * 16 + q * 4);
    }
}

// ---------------- stage 1: node projections ----------------------------------
__global__ void __launch_bounds__(256)
node_kernel(const float* __restrict__ h,
            const float* __restrict__ W,
            const float* __restrict__ b,
            int N,
            const unsigned long long* __restrict__ idx_probe) {
    __shared__ alignas(16) float sW[20 * D];        // 10 KB (Wu rows 0..9, Wv 10..19)
    __shared__ alignas(16) float sF[2][EPB * SSTR]; // 2 x 20 KB

    if (blockIdx.x == 0 && threadIdx.x == 0) {
        int ok = 1;
#pragma unroll
        for (int i = 0; i < 64; i++)
            if ((idx_probe[i] >> 32) != 0ULL) ok = 0;
        g_is64 = ok;
    }

    int t = threadIdx.x;
    long n0 = (long)blockIdx.x * EPB;

    stage_chunk(sF[0], h, n0, 0, t, N - 1);
    cpa_commit();

    for (int i = t; i < 20 * D; i += 256) {
        int c = i >> 7, k = i & 127;
        sW[i] = (c < 10) ? W[c * WIN + k] : W[(c - 10) * WIN + D + k];
    }

    unsigned long long acc[20];
#pragma unroll
    for (int c = 0; c < 20; c++) acc[c] = 0ULL;

#pragma unroll 1
    for (int ch = 0; ch < 8; ch++) {
        if (ch < 7) { stage_chunk(sF[(ch + 1) & 1], h, n0, ch + 1, t, N - 1); cpa_commit(); }
        if (ch < 7) cpa_wait1(); else cpa_wait0();
        __syncthreads();
        const float* buf = sF[ch & 1];
#pragma unroll
        for (int k4 = 0; k4 < 4; k4++) {
            ulonglong2 v = *(const ulonglong2*)&buf[t * SSTR + k4 * 4];
            int kf = ch * 16 + k4 * 4;
#pragma unroll
            for (int c = 0; c < 20; c++) {
                ulonglong2 w = *(const ulonglong2*)&sW[c * D + kf]; // broadcast
                ffma2(acc[c], v.x, w.x);
                ffma2(acc[c], v.y, w.y);
            }
        }
        __syncthreads();
    }

    long n = n0 + t;
    if (n >= N) return;
    float r[10], s[10];
#pragma unroll
    for (int c = 0; c < 10; c++) {
        r[c] = f2sum(acc[c]) + __ldg(b + c);
        s[c] = f2sum(acc[10 + c]);
    }
    float4* Pp = (float4*)(g_P + n * PSTR);
    float4* Qp = (float4*)(g_Q + n * PSTR);
    Pp[0] = make_float4(r[0], r[1], r[2], r[3]);
    Pp[1] = make_float4(r[4], r[5], r[6], r[7]);
    Pp[2] = make_float4(r[8], r[9], 0.f, 0.f);
    Qp[0] = make_float4(s[0], s[1], s[2], s[3]);
    Qp[1] = make_float4(s[4], s[5], s[6], s[7]);
    Qp[2] = make_float4(s[8], s[9], 0.f, 0.f);
}

// ---------------- stage 2: per-edge ------------------------------------------
__global__ void __launch_bounds__(256)
edge_kernel(const float* __restrict__ eh,
            const float* __restrict__ W,
            const void* __restrict__ src,
            const void* __restrict__ dst,
            float* __restrict__ out,
            int E) {
    __shared__ alignas(16) float sW[C * D];         // 5 KB
    __shared__ alignas(16) float sF[2][EPB * SSTR]; // 2 x 20 KB

    int t = threadIdx.x;
    long e0 = (long)blockIdx.x * EPB;

    stage_chunk(sF[0], eh, e0, 0, t, E - 1);
    cpa_commit();

    for (int i = t; i < C * D; i += 256) {
        int c = i >> 7, k = i & 127;
        sW[i] = W[c * WIN + 2 * D + k];
    }

    unsigned long long acc[C];
#pragma unroll
    for (int c = 0; c < C; c++) acc[c] = 0ULL;

#pragma unroll 1
    for (int ch = 0; ch < 8; ch++) {
        if (ch < 7) { stage_chunk(sF[(ch + 1) & 1], eh, e0, ch + 1, t, E - 1); cpa_commit(); }
        if (ch < 7) cpa_wait1(); else cpa_wait0();
        __syncthreads();
        const float* buf = sF[ch & 1];
#pragma unroll
        for (int k4 = 0; k4 < 4; k4++) {
            ulonglong2 v = *(const ulonglong2*)&buf[t * SSTR + k4 * 4];
            int kf = ch * 16 + k4 * 4;
#pragma unroll
            for (int c = 0; c < C; c++) {
                ulonglong2 w = *(const ulonglong2*)&sW[c * D + kf]; // broadcast
                ffma2(acc[c], v.x, w.x);
                ffma2(acc[c], v.y, w.y);
            }
        }
        __syncthreads();
    }

    long e = e0 + t;
    if (e >= E) return;

    long s, d;
    if (g_is64) {
        s = (long)((const long long*)src)[e];
        d = (long)((const long long*)dst)[e];
    } else {
        s = ((const int*)src)[e];
        d = ((const int*)dst)[e];
    }

    float r[10];
#pragma unroll
    for (int c = 0; c < C; c++) r[c] = f2sum(acc[c]);

    const float4* Pp = (const float4*)(g_P + s * PSTR);
    const float4* Qp = (const float4*)(g_Q + d * PSTR);
    float4 pa = Pp[0], pb = Pp[1], pc = Pp[2];
    float4 qa = Qp[0], qb = Qp[1], qc = Qp[2];
    r[0] += pa.x + qa.x; r[1] += pa.y + qa.y; r[2] += pa.z + qa.z; r[3] += pa.w + qa.w;
    r[4] += pb.x + qb.x; r[5] += pb.y + qb.y; r[6] += pb.z + qb.z; r[7] += pb.w + qb.w;
    r[8] += pc.x + qc.x; r[9] += pc.y + qc.y;

    float2* op = (float2*)(out + e * C);
#pragma unroll
    for (int i = 0; i < 5; i++)
        op[i] = make_float2(r[2 * i], r[2 * i + 1]);
}

extern "C" void kernel_launch(void* const* d_in, const int* in_sizes, int n_in,
                              void* d_out, int out_size) {
    const float* h   = (const float*)d_in[0];
    const float* eh  = (const float*)d_in[1];
    const float* Ww  = (const float*)d_in[2];
    const float* Wb  = (const float*)d_in[3];
    const void*  src = d_in[4];
    const void*  dst = d_in[5];

    int N = in_sizes[0] / D;   // 100000
    int E = in_sizes[1] / D;   // 600000

    node_kernel<<<(N + EPB - 1) / EPB, 256>>>(h, Ww, Wb, N,
                                              (const unsigned long long*)src);
    edge_kernel<<<(E + EPB - 1) / EPB, 256>>>(eh, Ww, src, dst, (float*)d_out, E);
}